// round 6
// baseline (speedup 1.0000x reference)
#include <cuda_runtime.h>
#include <cuda_bf16.h>
#include <stdint.h>

// ---------------------------------------------------------------------------
// GLCM layer, fully collapsed:
//   out[b, a*64+code, py, px] =
//     (1/1024) * sum_{t in 36x36 ext. window} wy(i)*wx(j) *
//                [ code(reflect(t)) == code ]
// where code(s) = 8*gl(s) + gl(clamp(s + shift_a)), gl = ceil(x/32)-1.
// ---------------------------------------------------------------------------

#define H 256
#define W 256
#define NPIX (H * W)
#define NB 2           // batch
#define LEVELS 8
#define L2 64
#define NANG 8
#define POOL 32
#define EXT 36         // 32 + 2*2 (box filter radius)
#define TILE 38        // 36 + shift halo (covers img coords [P0-3, P0+34])
#define TSTRIDE 40

__device__ int8_t g_gl[NB * NPIX];

// integer shifts derived from round(cos/-sin) for angles 0..315 step 45
__device__ __constant__ int c_shx[NANG] = { 1,  1,  0, -1, -1, -1,  0,  1 };
__device__ __constant__ int c_shy[NANG] = { 0, -1, -1, -1,  0,  1,  1,  1 };

// ---------------------------------------------------------------------------
// Pass 1: quantize. gl = ceil(x/32) - 1  (== searchsorted_left(bins,x)-1)
// ---------------------------------------------------------------------------
__global__ void quant_kernel(const float* __restrict__ x, int n) {
    int i = blockIdx.x * blockDim.x + threadIdx.x;
    if (i < n) {
        float v = x[i];
        // v * 2^-5 is exact; round-up-to-int == ceil
        int gl = __float2int_ru(v * 0.03125f) - 1;
        g_gl[i] = (int8_t)gl;   // in [-1, 7] for v in [0, 255)
    }
}

// ---------------------------------------------------------------------------
// Pass 2: one CTA per (batch, pool cell). Weighted 512-bin histogram.
// ---------------------------------------------------------------------------
__global__ __launch_bounds__(256, 1)
void glcm_pool_kernel(float* __restrict__ out) {
    const int px = blockIdx.x;        // 0..7
    const int py = blockIdx.y;        // 0..7
    const int b  = blockIdx.z;        // 0..1
    const int X0 = px * POOL;
    const int Y0 = py * POOL;
    const int tid = threadIdx.x;      // 256 threads, 8 warps

    __shared__ int8_t tile[TILE * TSTRIDE];
    __shared__ int    hist[8][NANG * L2];   // per-warp histograms

    // zero histograms (8*512 = 4096 ints)
    for (int i = tid; i < 8 * NANG * L2; i += 256)
        ((int*)hist)[i] = 0;

    // load gl tile covering image coords [Y0-3, Y0+34] x [X0-3, X0+34]
    const int8_t* gl = g_gl + b * NPIX;
    for (int i = tid; i < TILE * TILE; i += 256) {
        int r = i / TILE, c = i % TILE;
        int gy = Y0 - 3 + r; gy = max(0, min(gy, H - 1));
        int gx = X0 - 3 + c; gx = max(0, min(gx, W - 1));
        tile[r * TSTRIDE + c] = gl[gy * W + gx];
    }
    __syncthreads();

    int* whist = hist[tid >> 5];

    for (int pos = tid; pos < EXT * EXT; pos += 256) {
        int i = pos / EXT, j = pos % EXT;
        // separable triangular weights: 1,2,3,4,5,...,5,4,3,2,1
        int wgt = min(min(i + 1, EXT - i), 5) * min(min(j + 1, EXT - j), 5);

        // reflect-pad mapping (jnp.pad 'reflect': -k -> k, H-1+k -> H-1-k)
        int ty = Y0 - 2 + i; if (ty < 0) ty = -ty; else if (ty > H - 1) ty = 2 * (H - 1) - ty;
        int tx = X0 - 2 + j; if (tx < 0) tx = -tx; else if (tx > W - 1) tx = 2 * (W - 1) - tx;

        int g1 = tile[(ty - Y0 + 3) * TSTRIDE + (tx - X0 + 3)];

        #pragma unroll
        for (int a = 0; a < NANG; a++) {
            // shifted neighbor with clamp (border) padding
            int y2 = ty + c_shy[a]; y2 = max(0, min(y2, H - 1));
            int x2 = tx + c_shx[a]; x2 = max(0, min(x2, W - 1));
            int g2 = tile[(y2 - Y0 + 3) * TSTRIDE + (x2 - X0 + 3)];
            int code = (g1 << 3) + g2;      // may be <0 if x==0 at a pixel
            if ((unsigned)code < (unsigned)L2)
                atomicAdd(&whist[a * L2 + code], wgt);
        }
    }
    __syncthreads();

    // reduce per-warp histograms and write pooled output
    // out layout: [b][a*64+code][py][px], all fp32
    const float inv = 1.0f / (float)(POOL * POOL);
    for (int l = tid; l < NANG * L2; l += 256) {
        int s = 0;
        #pragma unroll
        for (int wp = 0; wp < 8; wp++) s += hist[wp][l];
        out[((b * (NANG * L2) + l) * 8 + py) * 8 + px] = (float)s * inv;
    }
}

extern "C" void kernel_launch(void* const* d_in, const int* in_sizes, int n_in,
                              void* d_out, int out_size) {
    const float* x = (const float*)d_in[0];
    float* out = (float*)d_out;
    int n = in_sizes[0];                       // 2*1*256*256 = 131072

    quant_kernel<<<(n + 255) / 256, 256>>>(x, n);
    dim3 grid(8, 8, NB);
    glcm_pool_kernel<<<grid, 256>>>(out);
}

// round 7
// speedup vs baseline: 1.0478x; 1.0478x over previous
#include <cuda_runtime.h>
#include <cuda_bf16.h>
#include <stdint.h>

// ---------------------------------------------------------------------------
// GLCM layer, fully collapsed:
//   out[b, a*64+code, py, px] =
//     (1/1024) * sum_{t in 36x36 ext. window} wy(i)*wx(j) *
//                [ code(reflect(t)) == code ]
// where code(s) = 8*gl(s) + gl(clamp(s + shift_a)), gl = ceil(x/32)-1.
// ---------------------------------------------------------------------------

#define H 256
#define W 256
#define NPIX (H * W)
#define NB 2           // batch
#define LEVELS 8
#define L2 64
#define NANG 8
#define POOL 32
#define EXT 36         // 32 + 2*2 (box filter radius)
#define TILE 38        // 36 + shift halo (covers img coords [P0-3, P0+34])
#define TSTRIDE 40

__device__ int8_t g_gl[NB * NPIX];

// integer shifts derived from round(cos/-sin) for angles 0..315 step 45
__device__ __constant__ int c_shx[NANG] = { 1,  1,  0, -1, -1, -1,  0,  1 };
__device__ __constant__ int c_shy[NANG] = { 0, -1, -1, -1,  0,  1,  1,  1 };

// ---------------------------------------------------------------------------
// Pass 1: quantize. gl = ceil(x/32) - 1  (== searchsorted_left(bins,x)-1)
// ---------------------------------------------------------------------------
__global__ void quant_kernel(const float* __restrict__ x, int n) {
    int i = blockIdx.x * blockDim.x + threadIdx.x;
    if (i < n) {
        float v = x[i];
        // v * 2^-5 is exact; round-up-to-int == ceil
        int gl = __float2int_ru(v * 0.03125f) - 1;
        g_gl[i] = (int8_t)gl;   // in [-1, 7] for v in [0, 255)
    }
}

// ---------------------------------------------------------------------------
// Pass 2: one CTA per (batch, pool cell). Weighted 512-bin histogram.
// ---------------------------------------------------------------------------
__global__ __launch_bounds__(256, 1)
void glcm_pool_kernel(float* __restrict__ out) {
    const int px = blockIdx.x;        // 0..7
    const int py = blockIdx.y;        // 0..7
    const int b  = blockIdx.z;        // 0..1
    const int X0 = px * POOL;
    const int Y0 = py * POOL;
    const int tid = threadIdx.x;      // 256 threads, 8 warps

    __shared__ int8_t tile[TILE * TSTRIDE];
    __shared__ int    hist[8][NANG * L2];   // per-warp histograms

    // zero histograms (8*512 = 4096 ints)
    for (int i = tid; i < 8 * NANG * L2; i += 256)
        ((int*)hist)[i] = 0;

    // load gl tile covering image coords [Y0-3, Y0+34] x [X0-3, X0+34]
    const int8_t* gl = g_gl + b * NPIX;
    for (int i = tid; i < TILE * TILE; i += 256) {
        int r = i / TILE, c = i % TILE;
        int gy = Y0 - 3 + r; gy = max(0, min(gy, H - 1));
        int gx = X0 - 3 + c; gx = max(0, min(gx, W - 1));
        tile[r * TSTRIDE + c] = gl[gy * W + gx];
    }
    __syncthreads();

    int* whist = hist[tid >> 5];

    for (int pos = tid; pos < EXT * EXT; pos += 256) {
        int i = pos / EXT, j = pos % EXT;
        // separable triangular weights: 1,2,3,4,5,...,5,4,3,2,1
        int wgt = min(min(i + 1, EXT - i), 5) * min(min(j + 1, EXT - j), 5);

        // reflect-pad mapping (jnp.pad 'reflect': -k -> k, H-1+k -> H-1-k)
        int ty = Y0 - 2 + i; if (ty < 0) ty = -ty; else if (ty > H - 1) ty = 2 * (H - 1) - ty;
        int tx = X0 - 2 + j; if (tx < 0) tx = -tx; else if (tx > W - 1) tx = 2 * (W - 1) - tx;

        int g1 = tile[(ty - Y0 + 3) * TSTRIDE + (tx - X0 + 3)];

        #pragma unroll
        for (int a = 0; a < NANG; a++) {
            // shifted neighbor with clamp (border) padding
            int y2 = ty + c_shy[a]; y2 = max(0, min(y2, H - 1));
            int x2 = tx + c_shx[a]; x2 = max(0, min(x2, W - 1));
            int g2 = tile[(y2 - Y0 + 3) * TSTRIDE + (x2 - X0 + 3)];
            int code = (g1 << 3) + g2;      // may be <0 if x==0 at a pixel
            if ((unsigned)code < (unsigned)L2)
                atomicAdd(&whist[a * L2 + code], wgt);
        }
    }
    __syncthreads();

    // reduce per-warp histograms and write pooled output
    // out layout: [b][a*64+code][py][px], all fp32
    const float inv = 1.0f / (float)(POOL * POOL);
    for (int l = tid; l < NANG * L2; l += 256) {
        int s = 0;
        #pragma unroll
        for (int wp = 0; wp < 8; wp++) s += hist[wp][l];
        out[((b * (NANG * L2) + l) * 8 + py) * 8 + px] = (float)s * inv;
    }
}

extern "C" void kernel_launch(void* const* d_in, const int* in_sizes, int n_in,
                              void* d_out, int out_size) {
    const float* x = (const float*)d_in[0];
    float* out = (float*)d_out;
    int n = in_sizes[0];                       // 2*1*256*256 = 131072

    quant_kernel<<<(n + 255) / 256, 256>>>(x, n);
    dim3 grid(8, 8, NB);
    glcm_pool_kernel<<<grid, 256>>>(out);
}

// round 8
// speedup vs baseline: 1.3605x; 1.2984x over previous
#include <cuda_runtime.h>
#include <cuda_bf16.h>
#include <stdint.h>

// ---------------------------------------------------------------------------
// GLCM layer, fully collapsed into ONE kernel:
//   out[b, a*64+code, py, px] =
//     (1/1024) * sum_{t in 36x36 ext. window} wy(i)*wx(j) *
//                [ code(reflect(t)) == code ]
// where code(s) = 8*gl(s) + gl(clamp(s + shift_a)), gl = ceil(x/32)-1.
//
// The tile is gathered with CLAMPED image coordinates, so the per-angle
// neighbor read needs no clamp: tile[(ty+shy)-Y0+3][(tx+shx)-X0+3] is
// exactly gl[clamp(ty+shy)][clamp(tx+shx)] for every CTA (all shifted
// indices provably lie in [0,38) including reflected border positions).
// ---------------------------------------------------------------------------

#define H 256
#define W 256
#define NPIX (H * W)
#define NB 2
#define L2 64
#define NANG 8
#define POOL 32
#define EXT 36          // 32 + 2*2 (box radius)
#define TILE 38         // 36 + 1-px shift halo  (image coords [P0-3, P0+34])
#define TSTRIDE 40
#define NT 512
#define NW 16           // warps = per-warp histograms

__global__ __launch_bounds__(NT, 1)
void glcm_kernel(const float* __restrict__ x, float* __restrict__ out) {
    const int px = blockIdx.x;        // 0..7
    const int py = blockIdx.y;        // 0..7
    const int b  = blockIdx.z;        // 0..1
    const int X0 = px * POOL;
    const int Y0 = py * POOL;
    const int tid = threadIdx.x;

    __shared__ int8_t tile[TILE * TSTRIDE];
    __shared__ int    hist[NW][NANG * L2];     // 16 x 512 ints = 32 KB

    // zero histograms (vectorized)
    for (int i = tid; i < NW * NANG * L2 / 4; i += NT)
        ((int4*)hist)[i] = make_int4(0, 0, 0, 0);

    // fused quantize + clamped gather of the 38x38 gray-level tile
    const float* xb = x + b * NPIX;
    for (int i = tid; i < TILE * TILE; i += NT) {
        int r = i / TILE, c = i % TILE;
        int gy = min(max(Y0 - 3 + r, 0), H - 1);
        int gx = min(max(X0 - 3 + c, 0), W - 1);
        // gl = ceil(v/32) - 1  ==  searchsorted_left(bins, v) - 1
        tile[r * TSTRIDE + c] =
            (int8_t)(__float2int_ru(xb[gy * W + gx] * 0.03125f) - 1);
    }
    __syncthreads();

    int* whist = hist[tid >> 5];

    for (int pos = tid; pos < EXT * EXT; pos += NT) {
        int i = pos / EXT, j = pos % EXT;
        // separable triangular weights 1,2,3,4,5,...,5,4,3,2,1
        int wgt = min(min(i + 1, EXT - i), 5) * min(min(j + 1, EXT - j), 5);

        // reflect-pad mapping for the box-filter position
        int ty = Y0 - 2 + i; if (ty < 0) ty = -ty; else if (ty > H - 1) ty = 2 * (H - 1) - ty;
        int tx = X0 - 2 + j; if (tx < 0) tx = -tx; else if (tx > W - 1) tx = 2 * (W - 1) - tx;

        const int8_t* base = &tile[(ty - Y0 + 3) * TSTRIDE + (tx - X0 + 3)];
        // 9 LDS with immediate offsets, fully pipelined
        int g1 = base[0];
        int g2[NANG];
        g2[0] = base[1];                 // shift ( 1,  0)
        g2[1] = base[-TSTRIDE + 1];      // shift ( 1, -1)
        g2[2] = base[-TSTRIDE];          // shift ( 0, -1)
        g2[3] = base[-TSTRIDE - 1];      // shift (-1, -1)
        g2[4] = base[-1];                // shift (-1,  0)
        g2[5] = base[TSTRIDE - 1];       // shift (-1,  1)
        g2[6] = base[TSTRIDE];           // shift ( 0,  1)
        g2[7] = base[TSTRIDE + 1];       // shift ( 1,  1)

        int c8 = g1 << 3;
        #pragma unroll
        for (int a = 0; a < NANG; a++) {
            int code = c8 + g2[a];       // negative iff g1==-1 (or g1==0,g2==-1)
            if ((unsigned)code < (unsigned)L2)
                atomicAdd(&whist[a * L2 + code], wgt);
        }
    }
    __syncthreads();

    // reduce 16 per-warp histograms; write pooled output
    const float inv = 1.0f / (float)(POOL * POOL);
    for (int l = tid; l < NANG * L2; l += NT) {
        int s = 0;
        #pragma unroll
        for (int wp = 0; wp < NW; wp++) s += hist[wp][l];
        out[((b * (NANG * L2) + l) * 8 + py) * 8 + px] = (float)s * inv;
    }
}

extern "C" void kernel_launch(void* const* d_in, const int* in_sizes, int n_in,
                              void* d_out, int out_size) {
    const float* x = (const float*)d_in[0];
    float* out = (float*)d_out;
    dim3 grid(8, 8, NB);
    glcm_kernel<<<grid, NT>>>(x, out);
}

// round 9
// speedup vs baseline: 1.6875x; 1.2404x over previous
#include <cuda_runtime.h>
#include <cuda_bf16.h>
#include <stdint.h>

// ---------------------------------------------------------------------------
// GLCM layer, fully collapsed into ONE kernel:
//   out[b, a*64+code, py, px] =
//     (1/1024) * sum_{t in 36x36 ext. window} wy(i)*wx(j) *
//                [ code(reflect(t)) == code ]
// where code(s) = 8*gl(s) + gl(clamp(s + shift_a)), gl = ceil(x/32)-1.
//
// Tile is gathered with CLAMPED image coordinates, so per-angle neighbor
// reads need no clamp: all shifted indices provably lie in [0,38).
// 1024 threads / 32 warps; warp PAIRS share one of 16 histograms (atomics
// keep it correct; keeps static SMEM under 48 KB).
// ---------------------------------------------------------------------------

#define H 256
#define W 256
#define NPIX (H * W)
#define NB 2
#define L2 64
#define NANG 8
#define POOL 32
#define EXT 36          // 32 + 2*2 (box radius)
#define TILE 38         // 36 + 1-px shift halo  (image coords [P0-3, P0+34])
#define TSTRIDE 40
#define NT 1024
#define NH 16           // histogram copies (one per warp pair)

__global__ __launch_bounds__(NT, 1)
void glcm_kernel(const float* __restrict__ x, float* __restrict__ out) {
    const int px = blockIdx.x;        // 0..7
    const int py = blockIdx.y;        // 0..7
    const int b  = blockIdx.z;        // 0..1
    const int X0 = px * POOL;
    const int Y0 = py * POOL;
    const int tid = threadIdx.x;

    __shared__ int8_t tile[TILE * TSTRIDE];
    __shared__ int    hist[NH][NANG * L2];     // 16 x 512 ints = 32 KB

    // zero histograms (vectorized; 2 int4 per thread)
    for (int i = tid; i < NH * NANG * L2 / 4; i += NT)
        ((int4*)hist)[i] = make_int4(0, 0, 0, 0);

    // fused quantize + clamped gather of the 38x38 gray-level tile
    const float* xb = x + b * NPIX;
    for (int i = tid; i < TILE * TILE; i += NT) {
        int r = i / TILE, c = i % TILE;
        int gy = min(max(Y0 - 3 + r, 0), H - 1);
        int gx = min(max(X0 - 3 + c, 0), W - 1);
        // gl = ceil(v/32) - 1  ==  searchsorted_left(bins, v) - 1
        tile[r * TSTRIDE + c] =
            (int8_t)(__float2int_ru(xb[gy * W + gx] * 0.03125f) - 1);
    }
    __syncthreads();

    int* whist = hist[tid >> 6];      // warp pair -> shared histogram

    // <=2 trips per thread (1296 positions over 1024 threads)
    for (int pos = tid; pos < EXT * EXT; pos += NT) {
        int i = pos / EXT, j = pos % EXT;
        // separable triangular weights 1,2,3,4,5,...,5,4,3,2,1
        int wgt = min(min(i + 1, EXT - i), 5) * min(min(j + 1, EXT - j), 5);

        // reflect-pad mapping for the box-filter position
        int ty = Y0 - 2 + i; if (ty < 0) ty = -ty; else if (ty > H - 1) ty = 2 * (H - 1) - ty;
        int tx = X0 - 2 + j; if (tx < 0) tx = -tx; else if (tx > W - 1) tx = 2 * (W - 1) - tx;

        const int8_t* base = &tile[(ty - Y0 + 3) * TSTRIDE + (tx - X0 + 3)];
        // 9 LDS with immediate offsets, fully pipelined
        int g1 = base[0];
        int g2[NANG];
        g2[0] = base[1];                 // shift ( 1,  0)
        g2[1] = base[-TSTRIDE + 1];      // shift ( 1, -1)
        g2[2] = base[-TSTRIDE];          // shift ( 0, -1)
        g2[3] = base[-TSTRIDE - 1];      // shift (-1, -1)
        g2[4] = base[-1];                // shift (-1,  0)
        g2[5] = base[TSTRIDE - 1];       // shift (-1,  1)
        g2[6] = base[TSTRIDE];           // shift ( 0,  1)
        g2[7] = base[TSTRIDE + 1];       // shift ( 1,  1)

        int c8 = g1 << 3;
        #pragma unroll
        for (int a = 0; a < NANG; a++) {
            int code = c8 + g2[a];       // negative iff g1==-1 (or g1==0,g2==-1)
            if ((unsigned)code < (unsigned)L2)
                atomicAdd(&whist[a * L2 + code], wgt);
        }
    }
    __syncthreads();

    // reduce 16 histograms; write pooled output (512 bins, threads < 512)
    const float inv = 1.0f / (float)(POOL * POOL);
    if (tid < NANG * L2) {
        int s = 0;
        #pragma unroll
        for (int hp = 0; hp < NH; hp++) s += hist[hp][tid];
        out[((b * (NANG * L2) + tid) * 8 + py) * 8 + px] = (float)s * inv;
    }
}

extern "C" void kernel_launch(void* const* d_in, const int* in_sizes, int n_in,
                              void* d_out, int out_size) {
    const float* x = (const float*)d_in[0];
    float* out = (float*)d_out;
    dim3 grid(8, 8, NB);
    glcm_kernel<<<grid, NT>>>(x, out);
}